// round 1
// baseline (speedup 1.0000x reference)
#include <cuda_runtime.h>
#include <cuda_bf16.h>
#include <math.h>

#define NN 100000
#define NE 600000
#define DD 128
#define TD 384
#define NG 64
#define ROUNDS 8

// ---------------- scratch (static device arrays; no allocation) ----------------
__device__ float g_x[NN * DD];        // node state
__device__ float g_S[NN * TD];        // per-type aggregated sums [n][t*128+i]
__device__ float g_agg[NN * DD];      // aggregated message after typed transform
__device__ float g_gi[NN * TD];
__device__ float g_gh[NN * TD];
__device__ float g_Wcat[TD * DD];     // [t*128+i][o] = msg_W[t][o][i]
__device__ float g_Wih_t[DD * TD];    // [i][o] = W_ih[o][i]
__device__ float g_Whh_t[DD * TD];
__device__ int   g_deg[NN];
__device__ int   g_rowoff[NN + 1];
__device__ int   g_cursor[NN];
__device__ int   g_packed[NE];        // src | (type<<20)
__device__ int   g_cnt[NN * 3];       // per-(node,type) in-edge counts
__device__ int   g_bsums[128];
__device__ float g_pooled[NG * DD];
__device__ int   g_gcount[NG];
__device__ int   g_gstart[NG + 1];

// ---------------- prep ----------------
__global__ void build_x(const int* __restrict__ x_type, const int* __restrict__ x_tok,
                        const float* __restrict__ x_small,
                        const float* __restrict__ type_emb, const float* __restrict__ tok_emb) {
    int n = blockIdx.x;
    int j = threadIdx.x;
    float v;
    if (j < 32)       v = type_emb[x_type[n] * 32 + j];
    else if (j < 64)  v = tok_emb[x_tok[n] * 32 + (j - 32)];
    else              v = x_small[n * 64 + (j - 64)];
    g_x[n * DD + j] = v;
}

__global__ void prep_weights(const float* __restrict__ msg_W,
                             const float* __restrict__ W_ih,
                             const float* __restrict__ W_hh) {
    int idx = blockIdx.x * blockDim.x + threadIdx.x;
    const int SZ = TD * DD; // 49152
    if (idx < SZ) {
        int k = idx >> 7;          // t*128+i
        int o = idx & 127;
        int t = k >> 7;
        int i = k & 127;
        g_Wcat[idx] = msg_W[t * 16384 + o * 128 + i];
    } else if (idx < 2 * SZ) {
        int q = idx - SZ;
        int i = q / TD;
        int o = q % TD;
        g_Wih_t[q] = W_ih[o * DD + i];
    } else if (idx < 3 * SZ) {
        int q = idx - 2 * SZ;
        int i = q / TD;
        int o = q % TD;
        g_Whh_t[q] = W_hh[o * DD + i];
    }
}

__global__ void zero_scratch() {
    int i = blockIdx.x * blockDim.x + threadIdx.x;
    if (i < NN) { g_deg[i] = 0; g_cursor[i] = 0; }
    if (i < 3 * NN) g_cnt[i] = 0;
    if (i < NG) g_gcount[i] = 0;
}

__global__ void count_deg(const int* __restrict__ ei) {
    int e = blockIdx.x * blockDim.x + threadIdx.x;
    if (e < NE) atomicAdd(&g_deg[ei[NE + e]], 1);
}

__global__ void count_graph(const int* __restrict__ batch) {
    int n = blockIdx.x * blockDim.x + threadIdx.x;
    if (n < NN) atomicAdd(&g_gcount[batch[n]], 1);
}

// ---------------- prefix scan (deg -> rowoff) ----------------
__global__ void scan_block() {
    __shared__ int sh[1024];
    int tid = threadIdx.x;
    int i = blockIdx.x * 1024 + tid;
    int v = (i < NN) ? g_deg[i] : 0;
    sh[tid] = v;
    __syncthreads();
    for (int off = 1; off < 1024; off <<= 1) {
        int t = (tid >= off) ? sh[tid - off] : 0;
        __syncthreads();
        sh[tid] += t;
        __syncthreads();
    }
    if (i < NN) g_rowoff[i + 1] = sh[tid];
    if (tid == 1023) g_bsums[blockIdx.x] = sh[1023];
}

__global__ void scan_sums(int nblk) {
    if (threadIdx.x == 0 && blockIdx.x == 0) {
        int acc = 0;
        for (int b = 0; b < nblk; b++) {
            int t = g_bsums[b];
            g_bsums[b] = acc;
            acc += t;
        }
    }
}

__global__ void add_off() {
    int i = blockIdx.x * blockDim.x + threadIdx.x;
    if (i < NN) g_rowoff[i + 1] += g_bsums[i >> 10];
    if (i == 0) g_rowoff[0] = 0;
}

__global__ void scatter_edges(const int* __restrict__ ei, const int* __restrict__ et) {
    int e = blockIdx.x * blockDim.x + threadIdx.x;
    if (e >= NE) return;
    int s = ei[e];
    int d = ei[NE + e];
    int t = et[e];
    int pos = g_rowoff[d] + atomicAdd(&g_cursor[d], 1);
    g_packed[pos] = s | (t << 20);
    atomicAdd(&g_cnt[d * 3 + t], 1);
}

__global__ void gscan() {
    if (threadIdx.x == 0 && blockIdx.x == 0) {
        int a = 0;
        g_gstart[0] = 0;
        for (int g = 0; g < NG; g++) { a += g_gcount[g]; g_gstart[g + 1] = a; }
    }
}

// ---------------- per-round kernels ----------------
__device__ __forceinline__ void f4add(float4& a, const float4& b) {
    a.x += b.x; a.y += b.y; a.z += b.z; a.w += b.w;
}

// One warp per dst node: sum x[src] into per-type accumulators. No atomics.
__global__ void aggregate_kernel() {
    int warp = (blockIdx.x * blockDim.x + threadIdx.x) >> 5;
    int lane = threadIdx.x & 31;
    if (warp >= NN) return;
    int beg = g_rowoff[warp];
    int end = g_rowoff[warp + 1];
    float4 a0 = make_float4(0.f, 0.f, 0.f, 0.f), a1 = a0, a2 = a0;
    const float4* x4 = (const float4*)g_x;
    for (int k = beg; k < end; k++) {
        int p = __ldg(&g_packed[k]);
        int s = p & 0xFFFFF;
        int t = p >> 20;
        float4 v = x4[s * 32 + lane];
        if (t == 0)      f4add(a0, v);
        else if (t == 1) f4add(a1, v);
        else             f4add(a2, v);
    }
    float4* S4 = (float4*)g_S;
    S4[warp * 96 + lane]      = a0;
    S4[warp * 96 + 32 + lane] = a1;
    S4[warp * 96 + 64 + lane] = a2;
}

// ---------------- SGEMM: C[M,Nout] = A[M,K] @ B[K,Nout] (+bias/+count-bias) ----------------
#define BM 128
#define BN 128
#define BK 16

__device__ __forceinline__ void sgemm_body(
    const float* __restrict__ A, const float* __restrict__ B, float* __restrict__ C,
    int M, int K, int Nout,
    const float* __restrict__ bias, const int* __restrict__ cnt, const float* __restrict__ msgb)
{
    __shared__ float As[2][BK][BM];
    __shared__ float Bs[2][BK][BN];

    const int tid = threadIdx.x;
    const int rowBase = blockIdx.x * BM;
    const int colBase = blockIdx.y * BN;
    const int tx = tid & 15;
    const int ty = tid >> 4;

    const int arow = tid >> 2;          // 0..63
    const int acol = (tid & 3) << 2;    // 0,4,8,12
    const int brow = tid >> 5;          // 0..7
    const int bcol = (tid & 31) << 2;   // 0..124

    float acc[8][8];
#pragma unroll
    for (int i = 0; i < 8; i++)
#pragma unroll
        for (int j = 0; j < 8; j++) acc[i][j] = 0.f;

    float4 pa[2], pb[2];

    // prologue: fetch tile 0
#pragma unroll
    for (int it = 0; it < 2; it++) {
        int grow = rowBase + arow + it * 64;
        pa[it] = make_float4(0.f, 0.f, 0.f, 0.f);
        if (grow < M) pa[it] = *(const float4*)(A + (size_t)grow * K + acol);
        pb[it] = *(const float4*)(B + (size_t)(brow + it * 8) * Nout + colBase + bcol);
    }
#pragma unroll
    for (int it = 0; it < 2; it++) {
        int r = arow + it * 64;
        As[0][acol + 0][r] = pa[it].x;
        As[0][acol + 1][r] = pa[it].y;
        As[0][acol + 2][r] = pa[it].z;
        As[0][acol + 3][r] = pa[it].w;
        *(float4*)&Bs[0][brow + it * 8][bcol] = pb[it];
    }
    __syncthreads();

    const int nk = K >> 4;
    for (int kt = 0; kt < nk; kt++) {
        const int buf = kt & 1;
        const int k0n = (kt + 1) << 4;
        if (kt + 1 < nk) {
#pragma unroll
            for (int it = 0; it < 2; it++) {
                int grow = rowBase + arow + it * 64;
                pa[it] = make_float4(0.f, 0.f, 0.f, 0.f);
                if (grow < M) pa[it] = *(const float4*)(A + (size_t)grow * K + k0n + acol);
                pb[it] = *(const float4*)(B + (size_t)(k0n + brow + it * 8) * Nout + colBase + bcol);
            }
        }
#pragma unroll
        for (int kk = 0; kk < BK; kk++) {
            float4 a0 = *(const float4*)&As[buf][kk][(ty << 2)];
            float4 a1 = *(const float4*)&As[buf][kk][64 + (ty << 2)];
            float4 b0 = *(const float4*)&Bs[buf][kk][(tx << 2)];
            float4 b1 = *(const float4*)&Bs[buf][kk][64 + (tx << 2)];
            float av[8] = {a0.x, a0.y, a0.z, a0.w, a1.x, a1.y, a1.z, a1.w};
            float bv[8] = {b0.x, b0.y, b0.z, b0.w, b1.x, b1.y, b1.z, b1.w};
#pragma unroll
            for (int i = 0; i < 8; i++)
#pragma unroll
                for (int j = 0; j < 8; j++)
                    acc[i][j] = fmaf(av[i], bv[j], acc[i][j]);
        }
        if (kt + 1 < nk) {
            const int nb = buf ^ 1;
#pragma unroll
            for (int it = 0; it < 2; it++) {
                int r = arow + it * 64;
                As[nb][acol + 0][r] = pa[it].x;
                As[nb][acol + 1][r] = pa[it].y;
                As[nb][acol + 2][r] = pa[it].z;
                As[nb][acol + 3][r] = pa[it].w;
                *(float4*)&Bs[nb][brow + it * 8][bcol] = pb[it];
            }
        }
        __syncthreads();
    }

    // epilogue
#pragma unroll
    for (int ii = 0; ii < 8; ii++) {
        int row = rowBase + ((ii < 4) ? (ty * 4 + ii) : (64 + ty * 4 + ii - 4));
        if (row >= M) continue;
        float c0 = 0.f, c1 = 0.f, c2 = 0.f;
        if (cnt) {
            c0 = (float)cnt[row * 3];
            c1 = (float)cnt[row * 3 + 1];
            c2 = (float)cnt[row * 3 + 2];
        }
#pragma unroll
        for (int h = 0; h < 2; h++) {
            int col = colBase + ((h == 0) ? (tx * 4) : (64 + tx * 4));
            float v[4] = {acc[ii][h * 4 + 0], acc[ii][h * 4 + 1],
                          acc[ii][h * 4 + 2], acc[ii][h * 4 + 3]};
            if (bias) {
#pragma unroll
                for (int c = 0; c < 4; c++) v[c] += bias[col + c];
            }
            if (cnt) {
#pragma unroll
                for (int c = 0; c < 4; c++)
                    v[c] += c0 * msgb[col + c] + c1 * msgb[128 + col + c] + c2 * msgb[256 + col + c];
            }
            float4 o = make_float4(v[0], v[1], v[2], v[3]);
            *(float4*)(C + (size_t)row * Nout + col) = o;
        }
    }
}

__global__ __launch_bounds__(256, 2)
void sgemm_agg_k(const float* __restrict__ msg_b) {
    sgemm_body(g_S, g_Wcat, g_agg, NN, TD, DD, nullptr, g_cnt, msg_b);
}
__global__ __launch_bounds__(256, 2)
void sgemm_gi_k(const float* __restrict__ b_ih) {
    sgemm_body(g_agg, g_Wih_t, g_gi, NN, DD, TD, b_ih, nullptr, nullptr);
}
__global__ __launch_bounds__(256, 2)
void sgemm_gh_k(const float* __restrict__ b_hh) {
    sgemm_body(g_x, g_Whh_t, g_gh, NN, DD, TD, b_hh, nullptr, nullptr);
}

__global__ void gru_kernel() {
    int idx = blockIdx.x * blockDim.x + threadIdx.x;
    if (idx >= NN * DD) return;
    int node = idx >> 7;
    int j = idx & 127;
    const float* gi = g_gi + (size_t)node * TD;
    const float* gh = g_gh + (size_t)node * TD;
    float ir = gi[j], iz = gi[128 + j], in_ = gi[256 + j];
    float hr = gh[j], hz = gh[128 + j], hn = gh[256 + j];
    float r = 1.f / (1.f + expf(-(ir + hr)));
    float z = 1.f / (1.f + expf(-(iz + hz)));
    float nn = tanhf(in_ + r * hn);
    float h = g_x[idx];
    g_x[idx] = (1.f - z) * nn + z * h;
}

// ---------------- readout ----------------
__global__ void pool_kernel() {
    int g = blockIdx.x;
    int j = threadIdx.x;
    int beg = g_gstart[g], end = g_gstart[g + 1];
    float s = 0.f;
    for (int nd = beg; nd < end; nd++) s += g_x[(size_t)nd * DD + j];
    int c = end - beg;
    float cf = (c > 0) ? (float)c : 1.f;
    g_pooled[g * DD + j] = s / cf;
}

__global__ void mlp_kernel(const float* __restrict__ pW1, const float* __restrict__ pb1,
                           const float* __restrict__ pW2, const float* __restrict__ pb2,
                           float* __restrict__ out) {
    int g = blockIdx.x;
    int j = threadIdx.x;
    __shared__ float sh[128];
    float acc = pb1[j];
    const float* pr = g_pooled + g * DD;
#pragma unroll 8
    for (int i = 0; i < DD; i++) acc = fmaf(pr[i], pW1[j * DD + i], acc);
    float h = acc > 0.f ? acc : 0.f;
    sh[j] = h * pW2[j];
    __syncthreads();
    for (int s = 64; s > 0; s >>= 1) {
        if (j < s) sh[j] += sh[j + s];
        __syncthreads();
    }
    if (j == 0) out[g] = sh[0] + pb2[0];
}

// ---------------- launch ----------------
extern "C" void kernel_launch(void* const* d_in, const int* in_sizes, int n_in,
                              void* d_out, int out_size) {
    const int*   x_type   = (const int*)d_in[0];
    const int*   x_tok    = (const int*)d_in[1];
    const float* x_small  = (const float*)d_in[2];
    const int*   edge_idx = (const int*)d_in[3];
    const int*   edge_typ = (const int*)d_in[4];
    const int*   batch    = (const int*)d_in[5];
    const float* type_emb = (const float*)d_in[6];
    const float* tok_emb  = (const float*)d_in[7];
    const float* msg_W    = (const float*)d_in[8];
    const float* msg_b    = (const float*)d_in[9];
    const float* W_ih     = (const float*)d_in[10];
    const float* W_hh     = (const float*)d_in[11];
    const float* b_ih     = (const float*)d_in[12];
    const float* b_hh     = (const float*)d_in[13];
    const float* pW1      = (const float*)d_in[14];
    const float* pb1      = (const float*)d_in[15];
    const float* pW2      = (const float*)d_in[16];
    const float* pb2      = (const float*)d_in[17];
    float* out = (float*)d_out;

    const int nblk_scan = (NN + 1023) / 1024;

    build_x<<<NN, 128>>>(x_type, x_tok, x_small, type_emb, tok_emb);
    prep_weights<<<(3 * TD * DD + 255) / 256, 256>>>(msg_W, W_ih, W_hh);
    zero_scratch<<<(3 * NN + 255) / 256, 256>>>();
    count_deg<<<(NE + 255) / 256, 256>>>(edge_idx);
    count_graph<<<(NN + 255) / 256, 256>>>(batch);
    scan_block<<<nblk_scan, 1024>>>();
    scan_sums<<<1, 32>>>(nblk_scan);
    add_off<<<(NN + 255) / 256, 256>>>();
    scatter_edges<<<(NE + 255) / 256, 256>>>(edge_idx, edge_typ);
    gscan<<<1, 32>>>();

    dim3 g_agg_grid((NN + BM - 1) / BM, 1);
    dim3 g_gate_grid((NN + BM - 1) / BM, TD / BN);

    for (int r = 0; r < ROUNDS; r++) {
        aggregate_kernel<<<(NN * 32 + 255) / 256, 256>>>();
        sgemm_agg_k<<<g_agg_grid, 256>>>(msg_b);
        sgemm_gi_k<<<g_gate_grid, 256>>>(b_ih);
        sgemm_gh_k<<<g_gate_grid, 256>>>(b_hh);
        gru_kernel<<<(NN * DD + 255) / 256, 256>>>();
    }

    pool_kernel<<<NG, 128>>>();
    mlp_kernel<<<NG, 128>>>(pW1, pb1, pW2, pb2, out);
}

// round 2
// speedup vs baseline: 1.3867x; 1.3867x over previous
#include <cuda_runtime.h>
#include <cuda_bf16.h>
#include <math.h>

#define NN 100000
#define NE 600000
#define DD 128
#define TD 384
#define NG 64
#define ROUNDS 8

// ---------------- scratch (static device arrays; no allocation) ----------------
__device__ float g_x[NN * DD];        // node state
__device__ float g_S[NN * TD];        // per-type aggregated sums [n][t*128+i]
__device__ float g_agg[NN * DD];      // aggregated message after typed transform
__device__ float g_gi[NN * TD];
__device__ float g_gh[NN * TD];
__device__ float g_Wcat[TD * DD];     // [t*128+i][o] = msg_W[t][o][i]
__device__ float g_Wih_t[DD * TD];    // [i][o] = W_ih[o][i]
__device__ float g_Whh_t[DD * TD];
__device__ int   g_deg[NN];
__device__ int   g_rowoff[NN + 1];
__device__ int   g_cursor[NN];
__device__ int   g_packed[NE];        // src | (type<<20)
__device__ int   g_cnt[NN * 3];       // per-(node,type) in-edge counts
__device__ int   g_bsums[128];
__device__ float g_pooled[NG * DD];
__device__ int   g_gcount[NG];
__device__ int   g_gstart[NG + 1];

// ---------------- prep ----------------
__global__ void build_x(const int* __restrict__ x_type, const int* __restrict__ x_tok,
                        const float* __restrict__ x_small,
                        const float* __restrict__ type_emb, const float* __restrict__ tok_emb) {
    int n = blockIdx.x;
    int j = threadIdx.x;
    float v;
    if (j < 32)       v = type_emb[x_type[n] * 32 + j];
    else if (j < 64)  v = tok_emb[x_tok[n] * 32 + (j - 32)];
    else              v = x_small[n * 64 + (j - 64)];
    g_x[n * DD + j] = v;
}

__global__ void prep_weights(const float* __restrict__ msg_W,
                             const float* __restrict__ W_ih,
                             const float* __restrict__ W_hh) {
    int idx = blockIdx.x * blockDim.x + threadIdx.x;
    const int SZ = TD * DD; // 49152
    if (idx < SZ) {
        int k = idx >> 7;          // t*128+i
        int o = idx & 127;
        int t = k >> 7;
        int i = k & 127;
        g_Wcat[idx] = msg_W[t * 16384 + o * 128 + i];
    } else if (idx < 2 * SZ) {
        int q = idx - SZ;
        int i = q / TD;
        int o = q % TD;
        g_Wih_t[q] = W_ih[o * DD + i];
    } else if (idx < 3 * SZ) {
        int q = idx - 2 * SZ;
        int i = q / TD;
        int o = q % TD;
        g_Whh_t[q] = W_hh[o * DD + i];
    }
}

__global__ void zero_scratch() {
    int i = blockIdx.x * blockDim.x + threadIdx.x;
    if (i < NN) { g_deg[i] = 0; g_cursor[i] = 0; }
    if (i < 3 * NN) g_cnt[i] = 0;
    if (i < NG) g_gcount[i] = 0;
}

__global__ void count_deg(const int* __restrict__ ei) {
    int e = blockIdx.x * blockDim.x + threadIdx.x;
    if (e < NE) atomicAdd(&g_deg[ei[NE + e]], 1);
}

__global__ void count_graph(const int* __restrict__ batch) {
    int n = blockIdx.x * blockDim.x + threadIdx.x;
    if (n < NN) atomicAdd(&g_gcount[batch[n]], 1);
}

// ---------------- prefix scan (deg -> rowoff) ----------------
__global__ void scan_block() {
    __shared__ int sh[1024];
    int tid = threadIdx.x;
    int i = blockIdx.x * 1024 + tid;
    int v = (i < NN) ? g_deg[i] : 0;
    sh[tid] = v;
    __syncthreads();
    for (int off = 1; off < 1024; off <<= 1) {
        int t = (tid >= off) ? sh[tid - off] : 0;
        __syncthreads();
        sh[tid] += t;
        __syncthreads();
    }
    if (i < NN) g_rowoff[i + 1] = sh[tid];
    if (tid == 1023) g_bsums[blockIdx.x] = sh[1023];
}

__global__ void scan_sums(int nblk) {
    if (threadIdx.x == 0 && blockIdx.x == 0) {
        int acc = 0;
        for (int b = 0; b < nblk; b++) {
            int t = g_bsums[b];
            g_bsums[b] = acc;
            acc += t;
        }
    }
}

__global__ void add_off() {
    int i = blockIdx.x * blockDim.x + threadIdx.x;
    if (i < NN) g_rowoff[i + 1] += g_bsums[i >> 10];
    if (i == 0) g_rowoff[0] = 0;
}

__global__ void scatter_edges(const int* __restrict__ ei, const int* __restrict__ et) {
    int e = blockIdx.x * blockDim.x + threadIdx.x;
    if (e >= NE) return;
    int s = ei[e];
    int d = ei[NE + e];
    int t = et[e];
    int pos = g_rowoff[d] + atomicAdd(&g_cursor[d], 1);
    g_packed[pos] = s | (t << 20);
    atomicAdd(&g_cnt[d * 3 + t], 1);
}

__global__ void gscan() {
    if (threadIdx.x == 0 && blockIdx.x == 0) {
        int a = 0;
        g_gstart[0] = 0;
        for (int g = 0; g < NG; g++) { a += g_gcount[g]; g_gstart[g + 1] = a; }
    }
}

// ---------------- per-round kernels ----------------
__device__ __forceinline__ void f4add(float4& a, const float4& b) {
    a.x += b.x; a.y += b.y; a.z += b.z; a.w += b.w;
}

// One warp per dst node: sum x[src] into per-type accumulators. No atomics.
__global__ void aggregate_kernel() {
    int warp = (blockIdx.x * blockDim.x + threadIdx.x) >> 5;
    int lane = threadIdx.x & 31;
    if (warp >= NN) return;
    int beg = g_rowoff[warp];
    int end = g_rowoff[warp + 1];
    float4 a0 = make_float4(0.f, 0.f, 0.f, 0.f), a1 = a0, a2 = a0;
    const float4* x4 = (const float4*)g_x;
    for (int k = beg; k < end; k++) {
        int p = __ldg(&g_packed[k]);
        int s = p & 0xFFFFF;
        int t = p >> 20;
        float4 v = x4[s * 32 + lane];
        if (t == 0)      f4add(a0, v);
        else if (t == 1) f4add(a1, v);
        else             f4add(a2, v);
    }
    float4* S4 = (float4*)g_S;
    S4[warp * 96 + lane]      = a0;
    S4[warp * 96 + 32 + lane] = a1;
    S4[warp * 96 + 64 + lane] = a2;
}

// ---------------- TF32 tensor-core GEMM ----------------
// C[M,Nout] = A[M,K] @ B[K,Nout] (+bias / +per-type count*msg_b)
// CTA tile 128x128xBK32, 256 thr, 8 warps of 64x32 (4x4 frags m16n8k8 tf32)
#define ASTRIDE 36
#define BSTRIDE 136
#define GEMM_SMEM ((2 * 128 * ASTRIDE + 2 * 32 * BSTRIDE) * 4)

__device__ __forceinline__ unsigned f2tf(float f) {
    unsigned r;
    asm("cvt.rna.tf32.f32 %0, %1;" : "=r"(r) : "f"(f));
    return r;
}

__device__ __forceinline__ void mma_tf32(float c[4], unsigned a0, unsigned a1,
                                         unsigned a2, unsigned a3,
                                         unsigned b0, unsigned b1) {
    asm volatile(
        "mma.sync.aligned.m16n8k8.row.col.f32.tf32.tf32.f32 "
        "{%0,%1,%2,%3}, {%4,%5,%6,%7}, {%8,%9}, {%0,%1,%2,%3};\n"
        : "+f"(c[0]), "+f"(c[1]), "+f"(c[2]), "+f"(c[3])
        : "r"(a0), "r"(a1), "r"(a2), "r"(a3), "r"(b0), "r"(b1));
}

__device__ __forceinline__ void tgemm_body(
    const float* __restrict__ A, const float* __restrict__ B, float* __restrict__ C,
    int M, int K, int Nout,
    const float* __restrict__ bias, const int* __restrict__ cnt, const float* __restrict__ msgb)
{
    extern __shared__ unsigned sh_u32[];
    unsigned* As = sh_u32;                       // [2][128][ASTRIDE]
    unsigned* Bs = sh_u32 + 2 * 128 * ASTRIDE;   // [2][32][BSTRIDE]

    const int tid = threadIdx.x;
    const int lane = tid & 31;
    const int wid = tid >> 5;
    const int warp_m = (wid & 1) * 64;
    const int warp_n = (wid >> 1) * 32;
    const int rowBase = blockIdx.x * 128;
    const int colBase = blockIdx.y * 128;

    // loader indices (4 float4 per thread for each of A,B)
    const int ar = tid >> 3;              // 0..31 (+32*i)
    const int ak = (tid & 7) << 2;        // 0,4,...,28
    const int bkr = tid >> 5;             // 0..7 (+8*i)
    const int bc = lane << 2;             // 0..124

    float acc[4][4][4];
#pragma unroll
    for (int i = 0; i < 4; i++)
#pragma unroll
        for (int j = 0; j < 4; j++)
#pragma unroll
            for (int c = 0; c < 4; c++) acc[i][j][c] = 0.f;

    float4 pa[4], pb[4];
    const float4 z4 = make_float4(0.f, 0.f, 0.f, 0.f);

#define FETCH(K0)                                                              \
    {                                                                          \
        _Pragma("unroll") for (int i = 0; i < 4; i++) {                        \
            int gr = rowBase + ar + i * 32;                                    \
            pa[i] = (gr < M) ? *(const float4*)(A + (size_t)gr * K + (K0) + ak) : z4; \
            pb[i] = *(const float4*)(B + (size_t)((K0) + bkr + i * 8) * Nout + colBase + bc); \
        }                                                                      \
    }

#define STS(BUF)                                                               \
    {                                                                          \
        unsigned* ap = As + (BUF) * 128 * ASTRIDE;                             \
        unsigned* bp = Bs + (BUF) * 32 * BSTRIDE;                              \
        _Pragma("unroll") for (int i = 0; i < 4; i++) {                        \
            int r = ar + i * 32;                                               \
            uint4 ua = make_uint4(f2tf(pa[i].x), f2tf(pa[i].y),                \
                                  f2tf(pa[i].z), f2tf(pa[i].w));               \
            *(uint4*)(ap + r * ASTRIDE + ak) = ua;                             \
            uint4 ub = make_uint4(f2tf(pb[i].x), f2tf(pb[i].y),                \
                                  f2tf(pb[i].z), f2tf(pb[i].w));               \
            *(uint4*)(bp + (bkr + i * 8) * BSTRIDE + bc) = ub;                 \
        }                                                                      \
    }

    FETCH(0);
    STS(0);
    __syncthreads();

    const int nk = K >> 5;
    for (int kt = 0; kt < nk; kt++) {
        const int buf = kt & 1;
        if (kt + 1 < nk) FETCH((kt + 1) << 5);

        const unsigned* ap = As + buf * 128 * ASTRIDE;
        const unsigned* bp = Bs + buf * 32 * BSTRIDE;
        const int gidx = lane >> 2;   // 0..7
        const int tig  = lane & 3;    // 0..3
#pragma unroll
        for (int ks = 0; ks < 4; ks++) {
            const int k = ks << 3;
            unsigned af[4][4], bf[4][2];
#pragma unroll
            for (int mf = 0; mf < 4; mf++) {
                const unsigned* p = ap + (warp_m + mf * 16 + gidx) * ASTRIDE + k + tig;
                af[mf][0] = p[0];
                af[mf][1] = p[8 * ASTRIDE];
                af[mf][2] = p[4];
                af[mf][3] = p[8 * ASTRIDE + 4];
            }
#pragma unroll
            for (int nf = 0; nf < 4; nf++) {
                const unsigned* p = bp + (k + tig) * BSTRIDE + warp_n + nf * 8 + gidx;
                bf[nf][0] = p[0];
                bf[nf][1] = p[4 * BSTRIDE];
            }
#pragma unroll
            for (int mf = 0; mf < 4; mf++)
#pragma unroll
                for (int nf = 0; nf < 4; nf++)
                    mma_tf32(acc[mf][nf], af[mf][0], af[mf][1], af[mf][2], af[mf][3],
                             bf[nf][0], bf[nf][1]);
        }

        if (kt + 1 < nk) STS(buf ^ 1);
        __syncthreads();
    }

    // epilogue
    const int gidx = lane >> 2;
    const int tig = lane & 3;
#pragma unroll
    for (int mf = 0; mf < 4; mf++) {
        int r0 = rowBase + warp_m + mf * 16 + gidx;
        int r1 = r0 + 8;
        float c00 = 0.f, c01 = 0.f, c02 = 0.f, c10 = 0.f, c11 = 0.f, c12 = 0.f;
        if (cnt) {
            if (r0 < M) { c00 = (float)cnt[r0 * 3]; c01 = (float)cnt[r0 * 3 + 1]; c02 = (float)cnt[r0 * 3 + 2]; }
            if (r1 < M) { c10 = (float)cnt[r1 * 3]; c11 = (float)cnt[r1 * 3 + 1]; c12 = (float)cnt[r1 * 3 + 2]; }
        }
#pragma unroll
        for (int nf = 0; nf < 4; nf++) {
            int col = colBase + warp_n + nf * 8 + tig * 2;
            float v0 = acc[mf][nf][0], v1 = acc[mf][nf][1];
            float w0 = acc[mf][nf][2], w1 = acc[mf][nf][3];
            if (bias) {
                float bb0 = bias[col], bb1 = bias[col + 1];
                v0 += bb0; v1 += bb1; w0 += bb0; w1 += bb1;
            }
            if (cnt) {
                float m00 = msgb[col], m10 = msgb[128 + col], m20 = msgb[256 + col];
                float m01 = msgb[col + 1], m11 = msgb[128 + col + 1], m21 = msgb[256 + col + 1];
                v0 += c00 * m00 + c01 * m10 + c02 * m20;
                v1 += c00 * m01 + c01 * m11 + c02 * m21;
                w0 += c10 * m00 + c11 * m10 + c12 * m20;
                w1 += c10 * m01 + c11 * m11 + c12 * m21;
            }
            if (r0 < M) *(float2*)(C + (size_t)r0 * Nout + col) = make_float2(v0, v1);
            if (r1 < M) *(float2*)(C + (size_t)r1 * Nout + col) = make_float2(w0, w1);
        }
    }
#undef FETCH
#undef STS
}

__global__ __launch_bounds__(256)
void tgemm_agg_k(const float* __restrict__ msg_b) {
    tgemm_body(g_S, g_Wcat, g_agg, NN, TD, DD, nullptr, g_cnt, msg_b);
}
__global__ __launch_bounds__(256)
void tgemm_gate_k(const float* __restrict__ b_ih, const float* __restrict__ b_hh) {
    if (blockIdx.z == 0)
        tgemm_body(g_agg, g_Wih_t, g_gi, NN, DD, TD, b_ih, nullptr, nullptr);
    else
        tgemm_body(g_x, g_Whh_t, g_gh, NN, DD, TD, b_hh, nullptr, nullptr);
}

__global__ void gru_kernel() {
    int idx = blockIdx.x * blockDim.x + threadIdx.x;
    if (idx >= NN * DD) return;
    int node = idx >> 7;
    int j = idx & 127;
    const float* gi = g_gi + (size_t)node * TD;
    const float* gh = g_gh + (size_t)node * TD;
    float ir = gi[j], iz = gi[128 + j], in_ = gi[256 + j];
    float hr = gh[j], hz = gh[128 + j], hn = gh[256 + j];
    float r = 1.f / (1.f + expf(-(ir + hr)));
    float z = 1.f / (1.f + expf(-(iz + hz)));
    float nn = tanhf(in_ + r * hn);
    float h = g_x[idx];
    g_x[idx] = (1.f - z) * nn + z * h;
}

// ---------------- readout ----------------
__global__ void pool_kernel() {
    int g = blockIdx.x;
    int j = threadIdx.x;
    int beg = g_gstart[g], end = g_gstart[g + 1];
    float s = 0.f;
    for (int nd = beg; nd < end; nd++) s += g_x[(size_t)nd * DD + j];
    int c = end - beg;
    float cf = (c > 0) ? (float)c : 1.f;
    g_pooled[g * DD + j] = s / cf;
}

__global__ void mlp_kernel(const float* __restrict__ pW1, const float* __restrict__ pb1,
                           const float* __restrict__ pW2, const float* __restrict__ pb2,
                           float* __restrict__ out) {
    int g = blockIdx.x;
    int j = threadIdx.x;
    __shared__ float sh[128];
    float acc = pb1[j];
    const float* pr = g_pooled + g * DD;
#pragma unroll 8
    for (int i = 0; i < DD; i++) acc = fmaf(pr[i], pW1[j * DD + i], acc);
    float h = acc > 0.f ? acc : 0.f;
    sh[j] = h * pW2[j];
    __syncthreads();
    for (int s = 64; s > 0; s >>= 1) {
        if (j < s) sh[j] += sh[j + s];
        __syncthreads();
    }
    if (j == 0) out[g] = sh[0] + pb2[0];
}

// ---------------- launch ----------------
extern "C" void kernel_launch(void* const* d_in, const int* in_sizes, int n_in,
                              void* d_out, int out_size) {
    const int*   x_type   = (const int*)d_in[0];
    const int*   x_tok    = (const int*)d_in[1];
    const float* x_small  = (const float*)d_in[2];
    const int*   edge_idx = (const int*)d_in[3];
    const int*   edge_typ = (const int*)d_in[4];
    const int*   batch    = (const int*)d_in[5];
    const float* type_emb = (const float*)d_in[6];
    const float* tok_emb  = (const float*)d_in[7];
    const float* msg_W    = (const float*)d_in[8];
    const float* msg_b    = (const float*)d_in[9];
    const float* W_ih     = (const float*)d_in[10];
    const float* W_hh     = (const float*)d_in[11];
    const float* b_ih     = (const float*)d_in[12];
    const float* b_hh     = (const float*)d_in[13];
    const float* pW1      = (const float*)d_in[14];
    const float* pb1      = (const float*)d_in[15];
    const float* pW2      = (const float*)d_in[16];
    const float* pb2      = (const float*)d_in[17];
    float* out = (float*)d_out;

    cudaFuncSetAttribute(tgemm_agg_k, cudaFuncAttributeMaxDynamicSharedMemorySize, GEMM_SMEM);
    cudaFuncSetAttribute(tgemm_gate_k, cudaFuncAttributeMaxDynamicSharedMemorySize, GEMM_SMEM);

    const int nblk_scan = (NN + 1023) / 1024;

    build_x<<<NN, 128>>>(x_type, x_tok, x_small, type_emb, tok_emb);
    prep_weights<<<(3 * TD * DD + 255) / 256, 256>>>(msg_W, W_ih, W_hh);
    zero_scratch<<<(3 * NN + 255) / 256, 256>>>();
    count_deg<<<(NE + 255) / 256, 256>>>(edge_idx);
    count_graph<<<(NN + 255) / 256, 256>>>(batch);
    scan_block<<<nblk_scan, 1024>>>();
    scan_sums<<<1, 32>>>(nblk_scan);
    add_off<<<(NN + 255) / 256, 256>>>();
    scatter_edges<<<(NE + 255) / 256, 256>>>(edge_idx, edge_typ);
    gscan<<<1, 32>>>();

    const int mblk = (NN + 127) / 128;
    dim3 agg_grid(mblk, 1);
    dim3 gate_grid(mblk, TD / 128, 2);

    for (int r = 0; r < ROUNDS; r++) {
        aggregate_kernel<<<(NN * 32 + 255) / 256, 256>>>();
        tgemm_agg_k<<<agg_grid, 256, GEMM_SMEM>>>(msg_b);
        tgemm_gate_k<<<gate_grid, 256, GEMM_SMEM>>>(b_ih, b_hh);
        gru_kernel<<<(NN * DD + 255) / 256, 256>>>();
    }

    pool_kernel<<<NG, 128>>>();
    mlp_kernel<<<NG, 128>>>(pW1, pb1, pW2, pb2, out);
}

// round 3
// speedup vs baseline: 2.0161x; 1.4539x over previous
#include <cuda_runtime.h>
#include <cuda_bf16.h>
#include <math.h>

#define NN 100000
#define NE 600000
#define DD 128
#define TD 384
#define NG 64
#define ROUNDS 8

// ---------------- scratch ----------------
__device__ float g_x[NN * DD];
__device__ float g_S[NN * TD];
__device__ float g_agg[NN * DD];
__device__ float g_Wcat[TD * DD];         // [t*128+i][o]
__device__ float g_Wcomb[3 * 256 * DD];   // [gate][k(0:128=hh,128:256=ih)][n]
__device__ int   g_deg[NN];
__device__ int   g_rowoff[NN + 1];
__device__ int   g_cursor[NN];
__device__ int   g_packed[NE];
__device__ int   g_cnt[NN * 3];
__device__ int   g_bsums[128];
__device__ int   g_scan_ctr;
__device__ float g_pooled[NG * DD];
__device__ int   g_gcount[NG];
__device__ int   g_gstart[NG + 1];

// ---------------- setup (compacted into 4 launches) ----------------
__global__ void mega_setup(const int* __restrict__ x_type, const int* __restrict__ x_tok,
                           const float* __restrict__ x_small,
                           const float* __restrict__ type_emb, const float* __restrict__ tok_emb,
                           const float* __restrict__ msg_W,
                           const float* __restrict__ W_ih, const float* __restrict__ W_hh) {
    long long idx = (long long)blockIdx.x * blockDim.x + threadIdx.x;
    const long long R0 = (long long)NN * 128;
    if (idx < R0) {
        int n = (int)(idx >> 7);
        int j = (int)(idx & 127);
        float v;
        if (j < 32)       v = type_emb[x_type[n] * 32 + j];
        else if (j < 64)  v = tok_emb[x_tok[n] * 32 + (j - 32)];
        else              v = x_small[n * 64 + (j - 64)];
        g_x[idx] = v;
        return;
    }
    long long i1 = idx - R0;
    if (i1 < TD * DD) {
        int k = (int)(i1 >> 7);
        int o = (int)(i1 & 127);
        int t = k >> 7;
        int i = k & 127;
        g_Wcat[i1] = msg_W[t * 16384 + o * 128 + i];
        return;
    }
    long long i2 = i1 - TD * DD;
    if (i2 < 3 * 256 * DD) {
        int g = (int)(i2 / (256 * DD));
        int rem = (int)(i2 - (long long)g * 256 * DD);
        int k = rem >> 7;
        int n = rem & 127;
        float v = (k < 128) ? W_hh[(g * 128 + n) * 128 + k]
                            : W_ih[(g * 128 + n) * 128 + (k - 128)];
        g_Wcomb[i2] = v;
        return;
    }
    long long i3 = i2 - 3 * 256 * DD;
    if (i3 < 3LL * NN) { g_cnt[i3] = 0; return; }
    long long i4 = i3 - 3LL * NN;
    if (i4 < NN) { g_deg[i4] = 0; g_cursor[i4] = 0; return; }
    long long i5 = i4 - NN;
    if (i5 < NG) { g_gcount[i5] = 0; return; }
    if (i5 == NG) g_scan_ctr = 0;
}

__global__ void counts_kernel(const int* __restrict__ ei, const int* __restrict__ batch) {
    int e = blockIdx.x * blockDim.x + threadIdx.x;
    if (e < NE) atomicAdd(&g_deg[ei[NE + e]], 1);
    if (e < NN) atomicAdd(&g_gcount[batch[e]], 1);
}

__global__ void scan_fused() {
    __shared__ int sh[1024];
    __shared__ int amLast;
    int tid = threadIdx.x;
    int i = blockIdx.x * 1024 + tid;
    int v = (i < NN) ? g_deg[i] : 0;
    sh[tid] = v;
    __syncthreads();
    for (int off = 1; off < 1024; off <<= 1) {
        int t = (tid >= off) ? sh[tid - off] : 0;
        __syncthreads();
        sh[tid] += t;
        __syncthreads();
    }
    if (i < NN) g_rowoff[i + 1] = sh[tid];
    if (tid == 1023) g_bsums[blockIdx.x] = sh[1023];
    __threadfence();
    if (tid == 0) {
        int t = atomicAdd(&g_scan_ctr, 1);
        amLast = (t == (int)gridDim.x - 1);
    }
    __syncthreads();
    if (amLast) {
        if (tid == 0) {
            int acc = 0;
            for (int b = 0; b < (int)gridDim.x; b++) {
                int t = g_bsums[b];
                g_bsums[b] = acc;
                acc += t;
            }
        }
        __syncthreads();
        for (int j = tid; j < NN; j += 1024)
            g_rowoff[j + 1] += g_bsums[j >> 10];
        if (tid == 0) g_rowoff[0] = 0;
    }
}

__global__ void scatter_kernel(const int* __restrict__ ei, const int* __restrict__ et) {
    if (blockIdx.x == 0 && threadIdx.x == 0) {
        int a = 0;
        g_gstart[0] = 0;
        for (int g = 0; g < NG; g++) { a += g_gcount[g]; g_gstart[g + 1] = a; }
    }
    int e = blockIdx.x * blockDim.x + threadIdx.x;
    if (e >= NE) return;
    int s = ei[e];
    int d = ei[NE + e];
    int t = et[e];
    int pos = g_rowoff[d] + atomicAdd(&g_cursor[d], 1);
    g_packed[pos] = s | (t << 20);
    atomicAdd(&g_cnt[d * 3 + t], 1);
}

// ---------------- aggregation ----------------
__device__ __forceinline__ void f4add(float4& a, const float4& b) {
    a.x += b.x; a.y += b.y; a.z += b.z; a.w += b.w;
}

__global__ void aggregate_kernel() {
    int warp = (blockIdx.x * blockDim.x + threadIdx.x) >> 5;
    int lane = threadIdx.x & 31;
    if (warp >= NN) return;
    int beg = g_rowoff[warp];
    int end = g_rowoff[warp + 1];
    float4 a0 = make_float4(0.f, 0.f, 0.f, 0.f), a1 = a0, a2 = a0;
    const float4* x4 = (const float4*)g_x;
    for (int k = beg; k < end; k++) {
        int p = __ldg(&g_packed[k]);
        int s = p & 0xFFFFF;
        int t = p >> 20;
        float4 v = x4[s * 32 + lane];
        if (t == 0)      f4add(a0, v);
        else if (t == 1) f4add(a1, v);
        else             f4add(a2, v);
    }
    float4* S4 = (float4*)g_S;
    S4[warp * 96 + lane]      = a0;
    S4[warp * 96 + 32 + lane] = a1;
    S4[warp * 96 + 64 + lane] = a2;
}

// ---------------- TF32 helpers ----------------
__device__ __forceinline__ unsigned f2tf(float f) {
    unsigned r;
    asm("cvt.rna.tf32.f32 %0, %1;" : "=r"(r) : "f"(f));
    return r;
}

__device__ __forceinline__ void mma_tf32(float c[4], unsigned a0, unsigned a1,
                                         unsigned a2, unsigned a3,
                                         unsigned b0, unsigned b1) {
    asm volatile(
        "mma.sync.aligned.m16n8k8.row.col.f32.tf32.tf32.f32 "
        "{%0,%1,%2,%3}, {%4,%5,%6,%7}, {%8,%9}, {%0,%1,%2,%3};\n"
        : "+f"(c[0]), "+f"(c[1]), "+f"(c[2]), "+f"(c[3])
        : "r"(a0), "r"(a1), "r"(a2), "r"(a3), "r"(b0), "r"(b1));
}

// ---------------- agg GEMM: agg = S @ Wcat + cnt*msg_b ----------------
#define ASTRIDE 36
#define BSTRIDE 136
#define GEMM_SMEM ((2 * 128 * ASTRIDE + 2 * 32 * BSTRIDE) * 4)

__global__ __launch_bounds__(256)
void tgemm_agg_k(const float* __restrict__ msgb) {
    extern __shared__ unsigned sh_u32[];
    unsigned* As = sh_u32;
    unsigned* Bs = sh_u32 + 2 * 128 * ASTRIDE;
    const float* A = g_S;
    const float* B = g_Wcat;
    float* C = g_agg;
    const int M = NN, K = TD, Nout = DD;

    const int tid = threadIdx.x;
    const int lane = tid & 31;
    const int wid = tid >> 5;
    const int warp_m = (wid & 1) * 64;
    const int warp_n = (wid >> 1) * 32;
    const int rowBase = blockIdx.x * 128;

    const int ar = tid >> 3;
    const int ak = (tid & 7) << 2;
    const int bkr = tid >> 5;
    const int bc = lane << 2;

    float acc[4][4][4];
#pragma unroll
    for (int i = 0; i < 4; i++)
#pragma unroll
        for (int j = 0; j < 4; j++)
#pragma unroll
            for (int c = 0; c < 4; c++) acc[i][j][c] = 0.f;

    float4 pa[4], pb[4];
    const float4 z4 = make_float4(0.f, 0.f, 0.f, 0.f);

#define FETCH(K0)                                                              \
    {                                                                          \
        _Pragma("unroll") for (int i = 0; i < 4; i++) {                        \
            int gr = rowBase + ar + i * 32;                                    \
            pa[i] = (gr < M) ? *(const float4*)(A + (size_t)gr * K + (K0) + ak) : z4; \
            pb[i] = *(const float4*)(B + (size_t)((K0) + bkr + i * 8) * Nout + bc); \
        }                                                                      \
    }
#define STS(BUF)                                                               \
    {                                                                          \
        unsigned* ap = As + (BUF) * 128 * ASTRIDE;                             \
        unsigned* bp = Bs + (BUF) * 32 * BSTRIDE;                              \
        _Pragma("unroll") for (int i = 0; i < 4; i++) {                        \
            int r = ar + i * 32;                                               \
            uint4 ua = make_uint4(f2tf(pa[i].x), f2tf(pa[i].y),                \
                                  f2tf(pa[i].z), f2tf(pa[i].w));               \
            *(uint4*)(ap + r * ASTRIDE + ak) = ua;                             \
            uint4 ub = make_uint4(f2tf(pb[i].x), f2tf(pb[i].y),                \
                                  f2tf(pb[i].z), f2tf(pb[i].w));               \
            *(uint4*)(bp + (bkr + i * 8) * BSTRIDE + bc) = ub;                 \
        }                                                                      \
    }

    FETCH(0);
    STS(0);
    __syncthreads();

    const int nk = K >> 5;
    const int gidx = lane >> 2;
    const int tig = lane & 3;
    for (int kt = 0; kt < nk; kt++) {
        const int buf = kt & 1;
        if (kt + 1 < nk) FETCH((kt + 1) << 5);
        const unsigned* ap = As + buf * 128 * ASTRIDE;
        const unsigned* bp = Bs + buf * 32 * BSTRIDE;
#pragma unroll
        for (int ks = 0; ks < 4; ks++) {
            const int k = ks << 3;
            unsigned af[4][4], bf[4][2];
#pragma unroll
            for (int mf = 0; mf < 4; mf++) {
                const unsigned* p = ap + (warp_m + mf * 16 + gidx) * ASTRIDE + k + tig;
                af[mf][0] = p[0];
                af[mf][1] = p[8 * ASTRIDE];
                af[mf][2] = p[4];
                af[mf][3] = p[8 * ASTRIDE + 4];
            }
#pragma unroll
            for (int nf = 0; nf < 4; nf++) {
                const unsigned* p = bp + (k + tig) * BSTRIDE + warp_n + nf * 8 + gidx;
                bf[nf][0] = p[0];
                bf[nf][1] = p[4 * BSTRIDE];
            }
#pragma unroll
            for (int mf = 0; mf < 4; mf++)
#pragma unroll
                for (int nf = 0; nf < 4; nf++)
                    mma_tf32(acc[mf][nf], af[mf][0], af[mf][1], af[mf][2], af[mf][3],
                             bf[nf][0], bf[nf][1]);
        }
        if (kt + 1 < nk) STS(buf ^ 1);
        __syncthreads();
    }

#pragma unroll
    for (int mf = 0; mf < 4; mf++) {
        int r0 = rowBase + warp_m + mf * 16 + gidx;
        int r1 = r0 + 8;
        float c00 = 0.f, c01 = 0.f, c02 = 0.f, c10 = 0.f, c11 = 0.f, c12 = 0.f;
        if (r0 < M) { c00 = (float)g_cnt[r0 * 3]; c01 = (float)g_cnt[r0 * 3 + 1]; c02 = (float)g_cnt[r0 * 3 + 2]; }
        if (r1 < M) { c10 = (float)g_cnt[r1 * 3]; c11 = (float)g_cnt[r1 * 3 + 1]; c12 = (float)g_cnt[r1 * 3 + 2]; }
#pragma unroll
        for (int nf = 0; nf < 4; nf++) {
            int col = warp_n + nf * 8 + tig * 2;
            float m00 = msgb[col], m10 = msgb[128 + col], m20 = msgb[256 + col];
            float m01 = msgb[col + 1], m11 = msgb[128 + col + 1], m21 = msgb[256 + col + 1];
            float v0 = acc[mf][nf][0] + c00 * m00 + c01 * m10 + c02 * m20;
            float v1 = acc[mf][nf][1] + c00 * m01 + c01 * m11 + c02 * m21;
            float w0 = acc[mf][nf][2] + c10 * m00 + c11 * m10 + c12 * m20;
            float w1 = acc[mf][nf][3] + c10 * m01 + c11 * m11 + c12 * m21;
            if (r0 < M) *(float2*)(C + (size_t)r0 * Nout + col) = make_float2(v0, v1);
            if (r1 < M) *(float2*)(C + (size_t)r1 * Nout + col) = make_float2(w0, w1);
        }
    }
#undef FETCH
#undef STS
}

// ---------------- fused gate-GEMM + GRU ----------------
// A = [x | agg] (128 rows x K=256, tf32 smem-resident). 4 phases:
//  P1: r  = sigmoid(K256 vs Wcomb[0] + b_ih_r + b_hh_r)
//  P2: t  = r * (x@Whh_n + b_hh_n)              (K 0..128 of Wcomb[2])
//  P3: nv = tanh(agg@Wih_n + b_ih_n + t)        (K 128..256 of Wcomb[2])
//  P4: z  = sigmoid(K256 vs Wcomb[1] + biases); x = (1-z)*nv + z*x_old
#define AST 260
#define BST 136
#define FUSED_SMEM ((128 * AST + 2 * 32 * BST) * 4)

__device__ __forceinline__ void fused_phase(
    const unsigned* __restrict__ As, unsigned* __restrict__ Bs,
    const float* __restrict__ Bsrc,  // global weights [klen rows][128]
    int kbeg, int nch,               // A k-offset; number of 32-k chunks
    int warp_m, int warp_n, int gidx, int tig, int tid,
    float acc[2][4][4])
{
#pragma unroll
    for (int i = 0; i < 2; i++)
#pragma unroll
        for (int j = 0; j < 4; j++)
#pragma unroll
            for (int c = 0; c < 4; c++) acc[i][j][c] = 0.f;

    const int bk = tid >> 4;          // 0..31
    const int bc = (tid & 15) * 8;    // 0..120

    float4 q0 = *(const float4*)(Bsrc + (size_t)bk * 128 + bc);
    float4 q1 = *(const float4*)(Bsrc + (size_t)bk * 128 + bc + 4);
    {
        unsigned* bp = Bs + bk * BST + bc;
        *(uint4*)bp = make_uint4(f2tf(q0.x), f2tf(q0.y), f2tf(q0.z), f2tf(q0.w));
        *(uint4*)(bp + 4) = make_uint4(f2tf(q1.x), f2tf(q1.y), f2tf(q1.z), f2tf(q1.w));
    }
    __syncthreads();

    for (int c = 0; c < nch; c++) {
        const int buf = c & 1;
        if (c + 1 < nch) {
            const float* src = Bsrc + (size_t)((c + 1) * 32 + bk) * 128 + bc;
            q0 = *(const float4*)src;
            q1 = *(const float4*)(src + 4);
        }
        const unsigned* bp = Bs + buf * 32 * BST;
        const int kk0 = kbeg + c * 32;
#pragma unroll
        for (int ks = 0; ks < 4; ks++) {
            const int k = ks << 3;
            unsigned af[2][4], bf[4][2];
#pragma unroll
            for (int mf = 0; mf < 2; mf++) {
                const unsigned* p = As + (warp_m + mf * 16 + gidx) * AST + kk0 + k + tig;
                af[mf][0] = p[0];
                af[mf][1] = p[8 * AST];
                af[mf][2] = p[4];
                af[mf][3] = p[8 * AST + 4];
            }
#pragma unroll
            for (int nf = 0; nf < 4; nf++) {
                const unsigned* p = bp + (k + tig) * BST + warp_n + nf * 8 + gidx;
                bf[nf][0] = p[0];
                bf[nf][1] = p[4 * BST];
            }
#pragma unroll
            for (int mf = 0; mf < 2; mf++)
#pragma unroll
                for (int nf = 0; nf < 4; nf++)
                    mma_tf32(acc[mf][nf], af[mf][0], af[mf][1], af[mf][2], af[mf][3],
                             bf[nf][0], bf[nf][1]);
        }
        if (c + 1 < nch) {
            unsigned* wp = Bs + (buf ^ 1) * 32 * BST + bk * BST + bc;
            *(uint4*)wp = make_uint4(f2tf(q0.x), f2tf(q0.y), f2tf(q0.z), f2tf(q0.w));
            *(uint4*)(wp + 4) = make_uint4(f2tf(q1.x), f2tf(q1.y), f2tf(q1.z), f2tf(q1.w));
        }
        __syncthreads();
    }
}

__device__ __forceinline__ float sigm(float v) { return 1.f / (1.f + expf(-v)); }

__global__ __launch_bounds__(512)
void fused_gru_k(const float* __restrict__ b_ih, const float* __restrict__ b_hh) {
    extern __shared__ unsigned sh_u32[];
    unsigned* As = sh_u32;                 // [128][AST]
    unsigned* Bs = sh_u32 + 128 * AST;     // [2][32][BST]

    const int tid = threadIdx.x;
    const int lane = tid & 31;
    const int wid = tid >> 5;
    const int warp_m = (wid & 3) * 32;
    const int warp_n = (wid >> 2) * 32;
    const int rowBase = blockIdx.x * 128;
    const int gidx = lane >> 2;
    const int tig = lane & 3;
    const float4 z4 = make_float4(0.f, 0.f, 0.f, 0.f);

    // Load A = [x | agg] as tf32
    {
        int r_ = tid >> 5;   // 0..15
        int c4 = lane;       // float4 index 0..31
#pragma unroll
        for (int i = 0; i < 8; i++) {
            int r = r_ + i * 16;
            int gr = rowBase + r;
            float4 vx = z4, va = z4;
            if (gr < NN) {
                vx = *(const float4*)(g_x + (size_t)gr * 128 + c4 * 4);
                va = *(const float4*)(g_agg + (size_t)gr * 128 + c4 * 4);
            }
            unsigned* p = As + r * AST + c4 * 4;
            *(uint4*)p = make_uint4(f2tf(vx.x), f2tf(vx.y), f2tf(vx.z), f2tf(vx.w));
            *(uint4*)(p + 128) = make_uint4(f2tf(va.x), f2tf(va.y), f2tf(va.z), f2tf(va.w));
        }
    }
    __syncthreads();

    float acc[2][4][4];
    float keep[2][4][4];

    // P1: gate r (K=256)
    fused_phase(As, Bs, g_Wcomb + 0 * 256 * DD, 0, 8, warp_m, warp_n, gidx, tig, tid, acc);
#pragma unroll
    for (int mf = 0; mf < 2; mf++)
#pragma unroll
        for (int nf = 0; nf < 4; nf++) {
            int col = warp_n + nf * 8 + tig * 2;
            float cb0 = b_ih[col] + b_hh[col];
            float cb1 = b_ih[col + 1] + b_hh[col + 1];
            keep[mf][nf][0] = sigm(acc[mf][nf][0] + cb0);
            keep[mf][nf][1] = sigm(acc[mf][nf][1] + cb1);
            keep[mf][nf][2] = sigm(acc[mf][nf][2] + cb0);
            keep[mf][nf][3] = sigm(acc[mf][nf][3] + cb1);
        }

    // P2: h_n = x @ Whh_n (K=0..128 of gate-n slab); t = r * (h_n + b_hh_n)
    fused_phase(As, Bs, g_Wcomb + 2 * 256 * DD, 0, 4, warp_m, warp_n, gidx, tig, tid, acc);
#pragma unroll
    for (int mf = 0; mf < 2; mf++)
#pragma unroll
        for (int nf = 0; nf < 4; nf++) {
            int col = warp_n + nf * 8 + tig * 2;
            float bb0 = b_hh[256 + col], bb1 = b_hh[256 + col + 1];
            keep[mf][nf][0] = keep[mf][nf][0] * (acc[mf][nf][0] + bb0);
            keep[mf][nf][1] = keep[mf][nf][1] * (acc[mf][nf][1] + bb1);
            keep[mf][nf][2] = keep[mf][nf][2] * (acc[mf][nf][2] + bb0);
            keep[mf][nf][3] = keep[mf][nf][3] * (acc[mf][nf][3] + bb1);
        }

    // P3: i_n = agg @ Wih_n (K=128..256); nv = tanh(i_n + b_ih_n + t)
    fused_phase(As, Bs, g_Wcomb + 2 * 256 * DD + 128 * DD, 128, 4, warp_m, warp_n, gidx, tig, tid, acc);
#pragma unroll
    for (int mf = 0; mf < 2; mf++)
#pragma unroll
        for (int nf = 0; nf < 4; nf++) {
            int col = warp_n + nf * 8 + tig * 2;
            float bb0 = b_ih[256 + col], bb1 = b_ih[256 + col + 1];
            keep[mf][nf][0] = tanhf(acc[mf][nf][0] + bb0 + keep[mf][nf][0]);
            keep[mf][nf][1] = tanhf(acc[mf][nf][1] + bb1 + keep[mf][nf][1]);
            keep[mf][nf][2] = tanhf(acc[mf][nf][2] + bb0 + keep[mf][nf][2]);
            keep[mf][nf][3] = tanhf(acc[mf][nf][3] + bb1 + keep[mf][nf][3]);
        }

    // P4: gate z (K=256); combine and write x
    fused_phase(As, Bs, g_Wcomb + 1 * 256 * DD, 0, 8, warp_m, warp_n, gidx, tig, tid, acc);
#pragma unroll
    for (int mf = 0; mf < 2; mf++) {
        int r0 = rowBase + warp_m + mf * 16 + gidx;
        int r1 = r0 + 8;
#pragma unroll
        for (int nf = 0; nf < 4; nf++) {
            int col = warp_n + nf * 8 + tig * 2;
            float cb0 = b_ih[128 + col] + b_hh[128 + col];
            float cb1 = b_ih[128 + col + 1] + b_hh[128 + col + 1];
            float z0 = sigm(acc[mf][nf][0] + cb0);
            float z1 = sigm(acc[mf][nf][1] + cb1);
            float z2 = sigm(acc[mf][nf][2] + cb0);
            float z3 = sigm(acc[mf][nf][3] + cb1);
            if (r0 < NN) {
                float2 h = *(const float2*)(g_x + (size_t)r0 * 128 + col);
                float o0 = (1.f - z0) * keep[mf][nf][0] + z0 * h.x;
                float o1 = (1.f - z1) * keep[mf][nf][1] + z1 * h.y;
                *(float2*)(g_x + (size_t)r0 * 128 + col) = make_float2(o0, o1);
            }
            if (r1 < NN) {
                float2 h = *(const float2*)(g_x + (size_t)r1 * 128 + col);
                float o2 = (1.f - z2) * keep[mf][nf][2] + z2 * h.x;
                float o3 = (1.f - z3) * keep[mf][nf][3] + z3 * h.y;
                *(float2*)(g_x + (size_t)r1 * 128 + col) = make_float2(o2, o3);
            }
        }
    }
}

// ---------------- readout ----------------
__global__ void pool_kernel() {
    int g = blockIdx.x;
    int j = threadIdx.x;
    int beg = g_gstart[g], end = g_gstart[g + 1];
    float s = 0.f;
    for (int nd = beg; nd < end; nd++) s += g_x[(size_t)nd * DD + j];
    int c = end - beg;
    float cf = (c > 0) ? (float)c : 1.f;
    g_pooled[g * DD + j] = s / cf;
}

__global__ void mlp_kernel(const float* __restrict__ pW1, const float* __restrict__ pb1,
                           const float* __restrict__ pW2, const float* __restrict__ pb2,
                           float* __restrict__ out) {
    int g = blockIdx.x;
    int j = threadIdx.x;
    __shared__ float sh[128];
    float acc = pb1[j];
    const float* pr = g_pooled + g * DD;
#pragma unroll 8
    for (int i = 0; i < DD; i++) acc = fmaf(pr[i], pW1[j * DD + i], acc);
    float h = acc > 0.f ? acc : 0.f;
    sh[j] = h * pW2[j];
    __syncthreads();
    for (int s = 64; s > 0; s >>= 1) {
        if (j < s) sh[j] += sh[j + s];
        __syncthreads();
    }
    if (j == 0) out[g] = sh[0] + pb2[0];
}

// ---------------- launch ----------------
extern "C" void kernel_launch(void* const* d_in, const int* in_sizes, int n_in,
                              void* d_out, int out_size) {
    const int*   x_type   = (const int*)d_in[0];
    const int*   x_tok    = (const int*)d_in[1];
    const float* x_small  = (const float*)d_in[2];
    const int*   edge_idx = (const int*)d_in[3];
    const int*   edge_typ = (const int*)d_in[4];
    const int*   batch    = (const int*)d_in[5];
    const float* type_emb = (const float*)d_in[6];
    const float* tok_emb  = (const float*)d_in[7];
    const float* msg_W    = (const float*)d_in[8];
    const float* msg_b    = (const float*)d_in[9];
    const float* W_ih     = (const float*)d_in[10];
    const float* W_hh     = (const float*)d_in[11];
    const float* b_ih     = (const float*)d_in[12];
    const float* b_hh     = (const float*)d_in[13];
    const float* pW1      = (const float*)d_in[14];
    const float* pb1      = (const float*)d_in[15];
    const float* pW2      = (const float*)d_in[16];
    const float* pb2      = (const float*)d_in[17];
    float* out = (float*)d_out;

    cudaFuncSetAttribute(tgemm_agg_k, cudaFuncAttributeMaxDynamicSharedMemorySize, GEMM_SMEM);
    cudaFuncSetAttribute(fused_gru_k, cudaFuncAttributeMaxDynamicSharedMemorySize, FUSED_SMEM);

    long long mega_total = (long long)NN * 128 + TD * DD + 3 * 256 * DD + 3LL * NN + NN + NG + 1;
    int mega_blocks = (int)((mega_total + 255) / 256);

    mega_setup<<<mega_blocks, 256>>>(x_type, x_tok, x_small, type_emb, tok_emb,
                                     msg_W, W_ih, W_hh);
    counts_kernel<<<(NE + 255) / 256, 256>>>(edge_idx, batch);
    scan_fused<<<(NN + 1023) / 1024, 1024>>>();
    scatter_kernel<<<(NE + 255) / 256, 256>>>(edge_idx, edge_typ);

    const int mblk = (NN + 127) / 128;
    for (int r = 0; r < ROUNDS; r++) {
        aggregate_kernel<<<(NN * 32 + 255) / 256, 256>>>();
        tgemm_agg_k<<<mblk, 256, GEMM_SMEM>>>(msg_b);
        fused_gru_k<<<mblk, 512, FUSED_SMEM>>>(b_ih, b_hh);
    }

    pool_kernel<<<NG, 128>>>();
    mlp_kernel<<<NG, 128>>>(pW1, pb1, pW2, pb2, out);
}